// round 3
// baseline (speedup 1.0000x reference)
#include <cuda_runtime.h>
#include <cstddef>

#define LSEQ 256
#define NB   8
#define NC   64
#define TRI  (LSEQ * (LSEQ - 1) / 2)   // 32640
#define WB   8                          // widths per block
#define DPAD 512                        // slack for discarded-lane reads

// t = max_c scores, packed-diagonal per batch: g_td[b*TRI + off1(w) + i]
__device__ float g_td[NB * TRI];

__host__ __device__ __forceinline__ int off1(int w) {
    return (w - 1) * LSEQ - ((w - 1) * w) / 2;
}

// ---------------------------------------------------------------------------
// Kernel 1: t[b,i,e] = max over C of scores[b,i,e,:], upper triangle only.
// ---------------------------------------------------------------------------
__global__ void max_kernel(const float* __restrict__ scores) {
    const int i    = blockIdx.x;
    const int b    = blockIdx.y;
    const int warp = threadIdx.x >> 5;
    const int lane = threadIdx.x & 31;

    for (int e = i + 1 + warp; e < LSEQ; e += 8) {
        const float* p = scores + (((size_t)b * LSEQ + i) * LSEQ + e) * NC;
        float v = fmaxf(p[lane], p[lane + 32]);
        #pragma unroll
        for (int o = 16; o > 0; o >>= 1)
            v = fmaxf(v, __shfl_xor_sync(0xffffffffu, v, o));
        if (lane == 0)
            g_td[b * TRI + off1(e - i) + i] = v;
    }
}

// ---------------------------------------------------------------------------
// Kernel 2: width-blocked CKY, one 1024-thread CTA per batch.
// Per block of WB widths [w0, w0+WB):
//   Phase A (bulk): split points j in [WB, w0) touch only old diagonals.
//     Thread (g = tid>>8, c = tid&255) accumulates acc[dw] over its quarter
//     of the j-range, reusing the left operand across all WB widths.
//     Right address for width w0+dw: rbase + dw*s0 - dw(dw-1)/2 (one IMAD).
//   Phase B (fixup): per width, remaining j in [1,WB) U [w0, w-1) (<=14),
//     group-split, combined with bulk partials + staged t term.
//     Max is idempotent, so overlapping j-ranges in early blocks are safe.
// ---------------------------------------------------------------------------
__global__ __launch_bounds__(1024, 1)
void dp_kernel(const int* __restrict__ lens, float* __restrict__ out) {
    const int b = blockIdx.x;
    extern __shared__ float S[];
    float* D  = S;                         // TRI + DPAD chart
    float* P  = D + TRI + DPAD;            // 4 * WB * 256 bulk partials
    float* T  = P + 4 * WB * 256;          // WB * 256 staged t terms
    float* P2 = T + WB * 256;              // 4 * 256 fixup partials
    const float* tb  = g_td + b * TRI;
    const int    tid = threadIdx.x;
    const int    c   = tid & 255;
    const int    g   = tid >> 8;

    // Width 1: s[i,i+1] = t[i,i+1]
    for (int i = tid; i < LSEQ - 1; i += 1024) D[i] = tb[i];
    __syncthreads();

    for (int w0 = 2; w0 < LSEQ; w0 += WB) {
        // ---- stage t for widths w0..w0+WB-1 (2 slots/thread, LDG fired now,
        //      STS after the bulk loop so the latency is hidden).
        float tval[2]; int tslot[2];
        #pragma unroll
        for (int q = 0; q < 2; ++q) {
            int s  = tid + q * 1024;
            int dw = s >> 8, cc = s & 255;
            int h  = w0 + dw; if (h > LSEQ - 1) h = LSEQ - 1;
            int mx = LSEQ - 1 - h;
            int ccc = cc > mx ? mx : cc;
            tval[q] = tb[off1(h) + ccc];
            tslot[q] = dw * 256 + cc;
        }

        // ---- Phase A: bulk partials over j in [WB, w0)
        float acc[WB];
        #pragma unroll
        for (int dw = 0; dw < WB; ++dw) acc[dw] = -1e30f;

        const int m = w0 - WB;
        if (m > 0) {
            const int jlo = WB + ((g * m) >> 2);
            const int jhi = WB + (((g + 1) * m) >> 2);
            int lidx  = off1(jlo) + c;          // left:  D[off1(j) + c]
            int lstep = LSEQ - jlo;
            int rbase = off1(w0 - jlo) + c + jlo;   // right at dw=0
            int rstep = (w0 - jlo) - LSEQ;
            int s0    = LSEQ - w0 + jlo;        // diag-to-diag stride at dw=0
            for (int j = jlo; j < jhi; ++j) {
                const float L = D[lidx];
                #pragma unroll
                for (int dw = 0; dw < WB; ++dw) {
                    int ridx = rbase + dw * s0 - (dw * (dw - 1)) / 2;
                    acc[dw] = fmaxf(acc[dw], L + D[ridx]);
                }
                lidx  += lstep; --lstep;
                rbase += rstep; --rstep;
                ++s0;
            }
        }
        #pragma unroll
        for (int dw = 0; dw < WB; ++dw)
            P[(g * WB + dw) * 256 + c] = acc[dw];
        T[tslot[0]] = tval[0];
        T[tslot[1]] = tval[1];
        __syncthreads();

        // ---- Phase B: per-width fixup + combine
        int offw = off1(w0);
        for (int dw = 0; dw < WB && (w0 + dw) < LSEQ; ++dw) {
            const int w = w0 + dw;
            const int n = LSEQ - w;
            float part = -1e30f;
            const int cnt = (WB - 1) + dw;
            for (int idx = g; idx < cnt; idx += 4) {
                int j = (idx < WB - 1) ? (idx + 1) : (w0 + idx - (WB - 1));
                if (j <= w - 1)
                    part = fmaxf(part, D[off1(j) + c] + D[off1(w - j) + c + j]);
            }
            P2[(g << 8) + c] = part;
            __syncthreads();
            if (g == 0 && c < n) {
                float v = fmaxf(fmaxf(P2[c],         P2[256 + c]),
                                fmaxf(P2[512 + c],   P2[768 + c]));
                v = fmaxf(v, fmaxf(fmaxf(P[(0 * WB + dw) * 256 + c],
                                         P[(1 * WB + dw) * 256 + c]),
                                   fmaxf(P[(2 * WB + dw) * 256 + c],
                                         P[(3 * WB + dw) * 256 + c])));
                D[offw + c] = v + T[dw * 256 + c];
            }
            __syncthreads();
            offw += n;
        }
    }

    if (tid == 0) {
        int len = lens[b];
        len = len < 1 ? 1 : (len > LSEQ - 1 ? LSEQ - 1 : len);
        out[b] = D[off1(len)];
    }
}

// ---------------------------------------------------------------------------
extern "C" void kernel_launch(void* const* d_in, const int* in_sizes, int n_in,
                              void* d_out, int out_size) {
    const float* scores = (const float*)d_in[0];
    const int*   lens   = (const int*)d_in[1];
    float*       out    = (float*)d_out;
    (void)in_sizes; (void)n_in; (void)out_size;

    const int smem = (TRI + DPAD + 4 * WB * 256 + WB * 256 + 4 * 256)
                     * (int)sizeof(float);
    cudaFuncSetAttribute(dp_kernel,
                         cudaFuncAttributeMaxDynamicSharedMemorySize, smem);

    max_kernel<<<dim3(LSEQ - 1, NB), 256>>>(scores);
    dp_kernel<<<NB, 1024, smem>>>(lens, out);
}